// round 6
// baseline (speedup 1.0000x reference)
#include <cuda_runtime.h>
#include <stdint.h>

// Problem constants
#define NB       64
#define NH       512
#define NW       512
#define NC       3
#define NUM_MASK 3072          // masked patches per image

// ---------------------------------------------------------------------------
// Single fused kernel.
// Grid (32 patch-row-PAIRS, NB=64 images); block = 384 threads.
// Each block handles TWO patch rows (16 image rows) of one image.
//
// Prologue: build the 128-patch masked bitmap for this pair of patch rows
// directly from mask_indices: each thread reads 2 int4 (8 indices) of this
// image's 3072 (coalesced; 12 KB slice shared by 32 blocks -> L2 resident),
// range-tests against the 128-patch window, atomicOr into 4 shared words.
//
// Main: a patch spans 8 consecutive rows sharing one mask bit. Each thread
// owns one float4 column; per band (8 rows):
//   - keep: 8x LDG.128 front-batched (MLP=8) + 8x STG.128
//   - drop: 8x STG.128 of zeros, image never read (saves 75% read traffic)
// Two bands processed sequentially (second band's loads overlap first
// band's store drain). Row stride = 384 float4 = 6144 B; fully coalesced.
// 32-bit indexing (total float4 count 12.6M < 2^31).
__global__ void __launch_bounds__(384)
random_mask_kernel(const float4* __restrict__ img,
                   const int*    __restrict__ mask_indices,
                   float4*       __restrict__ out) {
    const int prp = blockIdx.x;           // patch-row pair [0, 32)
    const int b   = blockIdx.y;           // image          [0, 64)
    const int t   = threadIdx.x;          // float4 col     [0, 384)

    // ---- build 128-bit masked-bitmap for this (image, patch-row pair) ----
    __shared__ uint32_t masked_bits[4];
    if (t < 4) masked_bits[t] = 0;
    __syncthreads();

    const int4* mi4 = (const int4*)(mask_indices + b * NUM_MASK);
    const int lo = prp << 7;              // first patch id of this pair
#pragma unroll
    for (int j = 0; j < 2; j++) {
        int4 v = mi4[t + j * 384];        // coalesced LDG.128, L2-hit
        unsigned d0 = (unsigned)(v.x - lo);
        unsigned d1 = (unsigned)(v.y - lo);
        unsigned d2 = (unsigned)(v.z - lo);
        unsigned d3 = (unsigned)(v.w - lo);
        if (d0 < 128u) atomicOr(&masked_bits[d0 >> 5], 1u << (d0 & 31));
        if (d1 < 128u) atomicOr(&masked_bits[d1 >> 5], 1u << (d1 & 31));
        if (d2 < 128u) atomicOr(&masked_bits[d2 >> 5], 1u << (d2 & 31));
        if (d3 < 128u) atomicOr(&masked_bits[d3 >> 5], 1u << (d3 & 31));
    }
    __syncthreads();

    const int pcol = t / 6;               // patch col: 6 float4 per patch

    // ---- stream two 8-row bands ----
    const int base0 = (b * NH + (prp << 4)) * 384 + t;

#pragma unroll
    for (int band = 0; band < 2; band++) {
        const int p = (band << 6) | pcol;
        const bool keep = !((masked_bits[p >> 5] >> (p & 31)) & 1u);

        const int base = base0 + band * (8 * 384);
        const float4* ip = img + base;
        float4*       op = out + base;

        if (keep) {
            float4 v[8];
#pragma unroll
            for (int r = 0; r < 8; r++) v[r] = __ldcs(ip + r * 384);
#pragma unroll
            for (int r = 0; r < 8; r++) __stcs(op + r * 384, v[r]);
        } else {
            const float4 z = make_float4(0.f, 0.f, 0.f, 0.f);
#pragma unroll
            for (int r = 0; r < 8; r++) __stcs(op + r * 384, z);
        }
    }
}

// ---------------------------------------------------------------------------
extern "C" void kernel_launch(void* const* d_in, const int* in_sizes, int n_in,
                              void* d_out, int out_size) {
    const float4* img = (const float4*)d_in[0];       // images [64,512,512,3] f32
    const int* mask_indices = (const int*)d_in[1];    // [64, 3072] i32
    float4* out = (float4*)d_out;

    dim3 grid(32, NB);                    // (patch-row pairs, images)
    random_mask_kernel<<<grid, 384>>>(img, mask_indices, out);
}

// round 7
// speedup vs baseline: 1.0143x; 1.0143x over previous
#include <cuda_runtime.h>
#include <stdint.h>

// Problem constants
#define NB       64
#define NH       512
#define NW       512
#define NC       3
#define NUM_MASK 3072          // masked patches per image

// ---------------------------------------------------------------------------
// Single fused kernel (R4 structure, deepened per-thread MLP).
// Grid (NPH=64 patch-rows, NB=64 images); block = 192 threads.
// Each thread owns TWO float4 columns of the 8-row patch band: t and t+192.
// Consecutive lanes -> consecutive addresses (perfect coalescing); the two
// columns belong to patches p=t/6 and p+32 (independent keep bits).
//
// Prologue: build this block's 64-patch masked bitmap directly from
// mask_indices: each thread reads 16 of this image's 3072 indices
// (coalesced scalar loads; 12 KB slice shared by 64 blocks -> L2 resident),
// range-tests against this patch-row, atomicOr into 2 shared words.
//
// Main: per thread, up to 16 front-batched predicated LDG.128 (MLP=16) then
// 16 STG.128. Masked patches never read the image (saves 75% read traffic).
// Row stride = 384 float4 = 6144 B.
__global__ void __launch_bounds__(192)
random_mask_kernel(const float4* __restrict__ img,
                   const int*    __restrict__ mask_indices,
                   float4*       __restrict__ out) {
    const int pr = blockIdx.x;            // patch row   [0, 64)
    const int b  = blockIdx.y;            // image       [0, 64)
    const int t  = threadIdx.x;           // [0, 192)

    // ---- build 64-bit masked-bitmap for this (image, patch-row) ----
    __shared__ uint32_t masked_bits[2];
    if (t < 2) masked_bits[t] = 0;
    __syncthreads();

    const int* mi = mask_indices + b * NUM_MASK;
    const int lo = pr << 6;               // first patch id of this row
#pragma unroll
    for (int j = 0; j < 16; j++) {
        int idx = mi[t + j * 192];        // coalesced, L2-resident
        unsigned d = (unsigned)(idx - lo);
        if (d < 64u) atomicOr(&masked_bits[d >> 5], 1u << (d & 31));
    }
    __syncthreads();

    const int p0 = t / 6;                 // patch of column t      [0, 32)
    const int p1 = p0 + 32;               // patch of column t+192
    const bool keepA = !((masked_bits[p0 >> 5] >> (p0 & 31)) & 1u);
    const bool keepB = !((masked_bits[p1 >> 5] >> (p1 & 31)) & 1u);

    // ---- stream the 8-row band, two columns per thread ----
    const long base = ((long)(b * NH + (pr << 3)) * 384) + t;
    const float4* ipA = img + base;
    const float4* ipB = img + base + 192;
    float4*       opA = out + base;
    float4*       opB = out + base + 192;

    const float4 z = make_float4(0.f, 0.f, 0.f, 0.f);
    float4 v[16];
#pragma unroll
    for (int r = 0; r < 16; r++) v[r] = z;

    if (keepA) {
#pragma unroll
        for (int r = 0; r < 8; r++) v[r] = __ldcs(ipA + r * 384);
    }
    if (keepB) {
#pragma unroll
        for (int r = 0; r < 8; r++) v[8 + r] = __ldcs(ipB + r * 384);
    }

#pragma unroll
    for (int r = 0; r < 8; r++) __stcs(opA + r * 384, v[r]);
#pragma unroll
    for (int r = 0; r < 8; r++) __stcs(opB + r * 384, v[8 + r]);
}

// ---------------------------------------------------------------------------
extern "C" void kernel_launch(void* const* d_in, const int* in_sizes, int n_in,
                              void* d_out, int out_size) {
    const float4* img = (const float4*)d_in[0];       // images [64,512,512,3] f32
    const int* mask_indices = (const int*)d_in[1];    // [64, 3072] i32
    float4* out = (float4*)d_out;

    dim3 grid(64, NB);                    // (patch-rows, images)
    random_mask_kernel<<<grid, 192>>>(img, mask_indices, out);
}